// round 16
// baseline (speedup 1.0000x reference)
#include <cuda_runtime.h>
#include <cuda_fp16.h>
#include <cstdint>

// ---------------------------------------------------------------------------
// ChebyKAN: out[n,o] = clip( sum_{i,d=0..4} T_d(tanh(clip(x[n,i]))) * coeffs[o,i,d] )
// N=16384, I=2048, O=2048.  T0==1 folded into bias; GEMM K = I*4 = 8192, fp16.
// ldmatrix + mma.sync.m16n8k16 (compute_103 baseline ISA; tcgen05 unavailable).
// R14 mainloop (2 chunks per __syncthreads/refill round — converged optimum
// across 6 sync-scheme experiments), with both per-round mbar waits hoisted
// to round start so the MMA stream runs uninterrupted within a round.
// ---------------------------------------------------------------------------

#define N_ROWS 16384
#define I_DIM  2048
#define O_DIM  2048
#define KDIM   8192
#define MT     128
#define NT     128
#define NPAIR  (KDIM / 64)           // 128 k-chunks of KC=64
#define NSTG   3
#define TILE_B 16384                 // 128 rows x 128 B (64 fp16)
#define STG_B  (2 * TILE_B)
#define SMEM_TOTAL (1024 + NSTG * STG_B)   // 99328
#define FEAT_BLOCKS (N_ROWS * I_DIM / 4 / 256)   // 32768
#define CLAMP10 10.0f

__device__ __align__(1024) unsigned char g_A[(size_t)N_ROWS * KDIM * 2]; // 256 MB
__device__ __align__(1024) unsigned char g_B[(size_t)O_DIM  * KDIM * 2]; //  32 MB
__device__ float g_bias[O_DIM];

static __device__ __forceinline__ uint32_t swz128(uint32_t off) {
    return off ^ ((off >> 3) & 0x70);
}
static __device__ __forceinline__ float clampf(float v) {
    return fminf(fmaxf(v, -CLAMP10), CLAMP10);
}
static __device__ __forceinline__ uint32_t smem_u32(const void* p) {
    return (uint32_t)__cvta_generic_to_shared(p);
}
static __device__ __forceinline__ void mbar_init(uint32_t a, uint32_t cnt) {
    asm volatile("mbarrier.init.shared.b64 [%0], %1;" :: "r"(a), "r"(cnt) : "memory");
}
static __device__ __forceinline__ void mbar_expect_tx(uint32_t a, uint32_t bytes) {
    asm volatile("mbarrier.arrive.expect_tx.shared.b64 _, [%0], %1;" :: "r"(a), "r"(bytes) : "memory");
}
static __device__ __forceinline__ void mbar_wait(uint32_t a, uint32_t parity) {
    asm volatile(
        "{\n\t.reg .pred P;\n\t"
        "WL_%=:\n\t"
        "mbarrier.try_wait.parity.acquire.cta.shared::cta.b64 P, [%0], %1, 0x989680;\n\t"
        "@P bra.uni WD_%=;\n\t"
        "bra.uni WL_%=;\n\t"
        "WD_%=:\n\t}"
        :: "r"(a), "r"(parity) : "memory");
}
static __device__ __forceinline__ void bulk_g2s(uint32_t dst, const void* src,
                                                uint32_t bytes, uint32_t mbar) {
    asm volatile(
        "cp.async.bulk.shared::cluster.global.mbarrier::complete_tx::bytes [%0], [%1], %2, [%3];"
        :: "r"(dst), "l"(src), "r"(bytes), "r"(mbar) : "memory");
}
static __device__ __forceinline__ void ldsm_x4(uint32_t& r0, uint32_t& r1,
                                               uint32_t& r2, uint32_t& r3, uint32_t a) {
    asm volatile("ldmatrix.sync.aligned.m8n8.x4.shared.b16 {%0,%1,%2,%3}, [%4];"
                 : "=r"(r0), "=r"(r1), "=r"(r2), "=r"(r3) : "r"(a));
}
static __device__ __forceinline__ void mma16816(float* d, const uint32_t* a,
                                                uint32_t b0, uint32_t b1) {
    asm volatile(
        "mma.sync.aligned.m16n8k16.row.col.f32.f16.f16.f32 "
        "{%0,%1,%2,%3}, {%4,%5,%6,%7}, {%8,%9}, {%0,%1,%2,%3};"
        : "+f"(d[0]), "+f"(d[1]), "+f"(d[2]), "+f"(d[3])
        : "r"(a[0]), "r"(a[1]), "r"(a[2]), "r"(a[3]), "r"(b0), "r"(b1));
}
static __device__ __forceinline__ float tanh_fast(float v) {
    float r;
    asm("tanh.approx.f32 %0, %1;" : "=f"(r) : "f"(v));
    return r;
}

// ---------------- fused prep: feature map blocks + B-repack/bias blocks ------
__global__ void prep_kernel(const float* __restrict__ x,
                            const float* __restrict__ coeffs) {
    if (blockIdx.x < FEAT_BLOCKS) {
        const int idx4 = blockIdx.x * 256 + threadIdx.x;     // over N*I/4
        const int n = idx4 >> 9;
        const int j = idx4 & 511;
        float4 xv = reinterpret_cast<const float4*>(x)[idx4];
        float vv[4] = {xv.x, xv.y, xv.z, xv.w};
        uint32_t u[8];
#pragma unroll
        for (int q = 0; q < 4; ++q) {
            float t  = tanh_fast(clampf(vv[q]));
            float t2 = 2.0f * t * t  - 1.0f;
            float t3 = 2.0f * t * t2 - t;
            float t4 = 2.0f * t * t3 - t2;
            __half2 p01 = __floats2half2_rn(t,  t2);
            __half2 p23 = __floats2half2_rn(t3, t4);
            u[q * 2 + 0] = *reinterpret_cast<uint32_t*>(&p01);
            u[q * 2 + 1] = *reinterpret_cast<uint32_t*>(&p23);
        }
        const int i0 = j * 4;
        const uint32_t off0 = (uint32_t)(n & 127) * 128u + (uint32_t)(i0 & 15) * 8u;
        const size_t  base  = ((size_t)((n >> 7) * NPAIR + (i0 >> 4))) << 14;
        *reinterpret_cast<uint4*>(g_A + base + swz128(off0)) =
            make_uint4(u[0], u[1], u[2], u[3]);
        *reinterpret_cast<uint4*>(g_A + base + swz128(off0 + 16)) =
            make_uint4(u[4], u[5], u[6], u[7]);
    } else {
        const int o = blockIdx.x - FEAT_BLOCKS;
        float bsum = 0.0f;
        for (int t = 0; t < I_DIM / 256; ++t) {
            int i = t * 256 + threadIdx.x;
            const float* c5 = coeffs + ((size_t)o * I_DIM + i) * 5;
            float c0 = c5[0];
            __half2 p01 = __floats2half2_rn(c5[1], c5[2]);
            __half2 p23 = __floats2half2_rn(c5[3], c5[4]);
            uint2 u = make_uint2(*reinterpret_cast<uint32_t*>(&p01),
                                 *reinterpret_cast<uint32_t*>(&p23));
            uint32_t off = (uint32_t)(o & 127) * 128u + (uint32_t)(i & 15) * 8u;
            size_t base  = ((size_t)((o >> 7) * NPAIR + (i >> 4))) << 14;
            *reinterpret_cast<uint2*>(g_B + base + swz128(off)) = u;
            bsum += c0;
        }
        __shared__ float red[256];
        red[threadIdx.x] = bsum;
        __syncthreads();
        for (int off = 128; off > 0; off >>= 1) {
            if (threadIdx.x < off) red[threadIdx.x] += red[threadIdx.x + off];
            __syncthreads();
        }
        if (threadIdx.x == 0) g_bias[o] = red[0];
    }
}

// ---------------- GEMM: 128x128 CTA tile, 8 warps, 2 chunks per sync ---------
__global__ void __launch_bounds__(256, 2)
gemm_kernel(float* __restrict__ C) {
    extern __shared__ __align__(1024) unsigned char smem[];
    const uint32_t sb = smem_u32(smem);
    const uint32_t stage0 = sb + 1024;

    const int tid  = threadIdx.x;
    const int wid  = tid >> 5, lane = tid & 31;
    const int wm   = wid & 3;
    const int wn   = wid >> 2;
    const int mtile = blockIdx.y, ntile = blockIdx.x;

    if (tid == 0) {
#pragma unroll
        for (int s = 0; s < NSTG; ++s) mbar_init(sb + s * 8, 1);
    }
    __syncthreads();

    const unsigned char* aSrc = g_A + ((size_t)mtile * NPAIR << 14);
    const unsigned char* bSrc = g_B + ((size_t)ntile * NPAIR << 14);

    if (tid == 0) {
#pragma unroll
        for (int p = 0; p < NSTG; ++p) {
            uint32_t fb = sb + p * 8;
            uint32_t dst = stage0 + p * STG_B;
            mbar_expect_tx(fb, STG_B);
            bulk_g2s(dst,          aSrc + ((size_t)p << 14), TILE_B, fb);
            bulk_g2s(dst + TILE_B, bSrc + ((size_t)p << 14), TILE_B, fb);
        }
    }

    float acc[2][8][4];
#pragma unroll
    for (int mi = 0; mi < 2; ++mi)
#pragma unroll
        for (int ni = 0; ni < 8; ++ni)
#pragma unroll
            for (int r = 0; r < 4; ++r) acc[mi][ni][r] = 0.0f;

    const int g = lane >> 3, r8 = lane & 7;
    const uint32_t aRow = (uint32_t)(wm * 32 + ((g & 1) << 3) + r8);
    const uint32_t bRow = (uint32_t)(wn * 64 + ((g >> 1) << 3) + r8);
    const uint32_t aKb  = (uint32_t)((g >> 1) << 4);
    const uint32_t bKb  = (uint32_t)((g & 1) << 4);

    for (int k = 0; k < NPAIR; k += 2) {
        // ---- hoisted waits: both chunks' data readiness checked up front ----
        // chunk k   -> stage k%3,  refilled 2 rounds ago (or prologue)
        // chunk k+1 -> stage (k+1)%3, refilled 1 round ago (or prologue)
        mbar_wait(sb + (k % NSTG) * 8,       (uint32_t)((k / NSTG) & 1));
        mbar_wait(sb + ((k + 1) % NSTG) * 8, (uint32_t)(((k + 1) / NSTG) & 1));

        // ---- consume chunks k and k+1 (uninterrupted MMA stream) ----
#pragma unroll
        for (int c = 0; c < 2; ++c) {
            const int kc = k + c;
            const int sp = kc % NSTG;
            const uint32_t stA = stage0 + sp * STG_B;
            const uint32_t stB = stA + TILE_B;

#pragma unroll
            for (int ks = 0; ks < 4; ++ks) {
                uint32_t a[2][4];
#pragma unroll
                for (int mi = 0; mi < 2; ++mi) {
                    uint32_t off = (aRow + mi * 16) * 128u + (uint32_t)(ks * 32) + aKb;
                    ldsm_x4(a[mi][0], a[mi][1], a[mi][2], a[mi][3], stA + swz128(off));
                }
                uint32_t b[4][4];
#pragma unroll
                for (int nj = 0; nj < 4; ++nj) {
                    uint32_t off = (bRow + nj * 16) * 128u + (uint32_t)(ks * 32) + bKb;
                    ldsm_x4(b[nj][0], b[nj][1], b[nj][2], b[nj][3], stB + swz128(off));
                }
#pragma unroll
                for (int mi = 0; mi < 2; ++mi)
#pragma unroll
                    for (int ni = 0; ni < 8; ++ni)
                        mma16816(acc[mi][ni], a[mi],
                                 b[ni >> 1][(ni & 1) * 2], b[ni >> 1][(ni & 1) * 2 + 1]);
            }
        }

        __syncthreads();   // all warps done reading stages k%3 and (k+1)%3
        if (tid == 0) {
#pragma unroll
            for (int c = 0; c < 2; ++c) {
                const int kn = k + c + NSTG;
                if (kn < NPAIR) {
                    const int sp = kn % NSTG;      // == (k+c)%3
                    const uint32_t fb = sb + sp * 8;
                    uint32_t dst = stage0 + sp * STG_B;
                    mbar_expect_tx(fb, STG_B);
                    bulk_g2s(dst,          aSrc + ((size_t)kn << 14), TILE_B, fb);
                    bulk_g2s(dst + TILE_B, bSrc + ((size_t)kn << 14), TILE_B, fb);
                }
            }
        }
    }

    // ---------------- epilogue: bias + clamp, float2 stores ------------------
    const int mBase = mtile * MT + wm * 32 + (lane >> 2);
    const int nBase = ntile * NT + wn * 64 + (lane & 3) * 2;

#pragma unroll
    for (int mi = 0; mi < 2; ++mi) {
#pragma unroll
        for (int ni = 0; ni < 8; ++ni) {
            const int n = nBase + ni * 8;
            const float b0 = g_bias[n], b1 = g_bias[n + 1];
            const int m0 = mBase + mi * 16;
            float2 v0, v1;
            v0.x = clampf(acc[mi][ni][0] + b0);
            v0.y = clampf(acc[mi][ni][1] + b1);
            v1.x = clampf(acc[mi][ni][2] + b0);
            v1.y = clampf(acc[mi][ni][3] + b1);
            *reinterpret_cast<float2*>(C + (size_t)m0 * O_DIM + n)       = v0;
            *reinterpret_cast<float2*>(C + (size_t)(m0 + 8) * O_DIM + n) = v1;
        }
    }
}

// ---------------------------------------------------------------------------
extern "C" void kernel_launch(void* const* d_in, const int* in_sizes, int n_in,
                              void* d_out, int out_size) {
    const float* x      = (const float*)d_in[0];
    const float* coeffs = (const float*)d_in[1];
    float* out          = (float*)d_out;

    cudaFuncSetAttribute(gemm_kernel, cudaFuncAttributeMaxDynamicSharedMemorySize, SMEM_TOTAL);

    prep_kernel<<<FEAT_BLOCKS + O_DIM, 256>>>(x, coeffs);
    gemm_kernel<<<dim3(O_DIM / NT, N_ROWS / MT), 256, SMEM_TOTAL>>>(out);
}

// round 17
// speedup vs baseline: 1.1120x; 1.1120x over previous
#include <cuda_runtime.h>
#include <cuda_fp16.h>
#include <cstdint>

// ---------------------------------------------------------------------------
// ChebyKAN: out[n,o] = clip( sum_{i,d=0..4} T_d(tanh(clip(x[n,i]))) * coeffs[o,i,d] )
// N=16384, I=2048, O=2048.  T0==1 folded into bias; GEMM K = I*4 = 8192, fp16.
// ldmatrix + mma.sync.m16n8k16 (compute_103 baseline ISA; tcgen05 unavailable).
// FINAL (R14 config, measured optimum across 7 mainloop variants):
//  - 128x128 CTA tile, 8 warps (4m x 2n), 3-stage cp.async.bulk ring
//  - 2 k-chunks consumed per __syncthreads/refill round (64 rounds)
//  - mid-round mbar waits kept in place (they overlap TMA latency with MMAs)
//  - fused prep kernel: tanh.approx feature map + B repack + bias, one launch
// ---------------------------------------------------------------------------

#define N_ROWS 16384
#define I_DIM  2048
#define O_DIM  2048
#define KDIM   8192
#define MT     128
#define NT     128
#define NPAIR  (KDIM / 64)           // 128 k-chunks of KC=64
#define NSTG   3
#define TILE_B 16384                 // 128 rows x 128 B (64 fp16)
#define STG_B  (2 * TILE_B)
#define SMEM_TOTAL (1024 + NSTG * STG_B)   // 99328
#define FEAT_BLOCKS (N_ROWS * I_DIM / 4 / 256)   // 32768
#define CLAMP10 10.0f

__device__ __align__(1024) unsigned char g_A[(size_t)N_ROWS * KDIM * 2]; // 256 MB
__device__ __align__(1024) unsigned char g_B[(size_t)O_DIM  * KDIM * 2]; //  32 MB
__device__ float g_bias[O_DIM];

static __device__ __forceinline__ uint32_t swz128(uint32_t off) {
    return off ^ ((off >> 3) & 0x70);
}
static __device__ __forceinline__ float clampf(float v) {
    return fminf(fmaxf(v, -CLAMP10), CLAMP10);
}
static __device__ __forceinline__ uint32_t smem_u32(const void* p) {
    return (uint32_t)__cvta_generic_to_shared(p);
}
static __device__ __forceinline__ void mbar_init(uint32_t a, uint32_t cnt) {
    asm volatile("mbarrier.init.shared.b64 [%0], %1;" :: "r"(a), "r"(cnt) : "memory");
}
static __device__ __forceinline__ void mbar_expect_tx(uint32_t a, uint32_t bytes) {
    asm volatile("mbarrier.arrive.expect_tx.shared.b64 _, [%0], %1;" :: "r"(a), "r"(bytes) : "memory");
}
static __device__ __forceinline__ void mbar_wait(uint32_t a, uint32_t parity) {
    asm volatile(
        "{\n\t.reg .pred P;\n\t"
        "WL_%=:\n\t"
        "mbarrier.try_wait.parity.acquire.cta.shared::cta.b64 P, [%0], %1, 0x989680;\n\t"
        "@P bra.uni WD_%=;\n\t"
        "bra.uni WL_%=;\n\t"
        "WD_%=:\n\t}"
        :: "r"(a), "r"(parity) : "memory");
}
static __device__ __forceinline__ void bulk_g2s(uint32_t dst, const void* src,
                                                uint32_t bytes, uint32_t mbar) {
    asm volatile(
        "cp.async.bulk.shared::cluster.global.mbarrier::complete_tx::bytes [%0], [%1], %2, [%3];"
        :: "r"(dst), "l"(src), "r"(bytes), "r"(mbar) : "memory");
}
static __device__ __forceinline__ void ldsm_x4(uint32_t& r0, uint32_t& r1,
                                               uint32_t& r2, uint32_t& r3, uint32_t a) {
    asm volatile("ldmatrix.sync.aligned.m8n8.x4.shared.b16 {%0,%1,%2,%3}, [%4];"
                 : "=r"(r0), "=r"(r1), "=r"(r2), "=r"(r3) : "r"(a));
}
static __device__ __forceinline__ void mma16816(float* d, const uint32_t* a,
                                                uint32_t b0, uint32_t b1) {
    asm volatile(
        "mma.sync.aligned.m16n8k16.row.col.f32.f16.f16.f32 "
        "{%0,%1,%2,%3}, {%4,%5,%6,%7}, {%8,%9}, {%0,%1,%2,%3};"
        : "+f"(d[0]), "+f"(d[1]), "+f"(d[2]), "+f"(d[3])
        : "r"(a[0]), "r"(a[1]), "r"(a[2]), "r"(a[3]), "r"(b0), "r"(b1));
}
static __device__ __forceinline__ float tanh_fast(float v) {
    float r;
    asm("tanh.approx.f32 %0, %1;" : "=f"(r) : "f"(v));
    return r;
}

// ---------------- fused prep: feature map blocks + B-repack/bias blocks ------
__global__ void prep_kernel(const float* __restrict__ x,
                            const float* __restrict__ coeffs) {
    if (blockIdx.x < FEAT_BLOCKS) {
        const int idx4 = blockIdx.x * 256 + threadIdx.x;     // over N*I/4
        const int n = idx4 >> 9;
        const int j = idx4 & 511;
        float4 xv = reinterpret_cast<const float4*>(x)[idx4];
        float vv[4] = {xv.x, xv.y, xv.z, xv.w};
        uint32_t u[8];
#pragma unroll
        for (int q = 0; q < 4; ++q) {
            float t  = tanh_fast(clampf(vv[q]));
            float t2 = 2.0f * t * t  - 1.0f;
            float t3 = 2.0f * t * t2 - t;
            float t4 = 2.0f * t * t3 - t2;
            __half2 p01 = __floats2half2_rn(t,  t2);
            __half2 p23 = __floats2half2_rn(t3, t4);
            u[q * 2 + 0] = *reinterpret_cast<uint32_t*>(&p01);
            u[q * 2 + 1] = *reinterpret_cast<uint32_t*>(&p23);
        }
        const int i0 = j * 4;
        const uint32_t off0 = (uint32_t)(n & 127) * 128u + (uint32_t)(i0 & 15) * 8u;
        const size_t  base  = ((size_t)((n >> 7) * NPAIR + (i0 >> 4))) << 14;
        *reinterpret_cast<uint4*>(g_A + base + swz128(off0)) =
            make_uint4(u[0], u[1], u[2], u[3]);
        *reinterpret_cast<uint4*>(g_A + base + swz128(off0 + 16)) =
            make_uint4(u[4], u[5], u[6], u[7]);
    } else {
        const int o = blockIdx.x - FEAT_BLOCKS;
        float bsum = 0.0f;
        for (int t = 0; t < I_DIM / 256; ++t) {
            int i = t * 256 + threadIdx.x;
            const float* c5 = coeffs + ((size_t)o * I_DIM + i) * 5;
            float c0 = c5[0];
            __half2 p01 = __floats2half2_rn(c5[1], c5[2]);
            __half2 p23 = __floats2half2_rn(c5[3], c5[4]);
            uint2 u = make_uint2(*reinterpret_cast<uint32_t*>(&p01),
                                 *reinterpret_cast<uint32_t*>(&p23));
            uint32_t off = (uint32_t)(o & 127) * 128u + (uint32_t)(i & 15) * 8u;
            size_t base  = ((size_t)((o >> 7) * NPAIR + (i >> 4))) << 14;
            *reinterpret_cast<uint2*>(g_B + base + swz128(off)) = u;
            bsum += c0;
        }
        __shared__ float red[256];
        red[threadIdx.x] = bsum;
        __syncthreads();
        for (int off = 128; off > 0; off >>= 1) {
            if (threadIdx.x < off) red[threadIdx.x] += red[threadIdx.x + off];
            __syncthreads();
        }
        if (threadIdx.x == 0) g_bias[o] = red[0];
    }
}

// ---------------- GEMM: 128x128 CTA tile, 8 warps, 2 chunks per sync ---------
__global__ void __launch_bounds__(256, 2)
gemm_kernel(float* __restrict__ C) {
    extern __shared__ __align__(1024) unsigned char smem[];
    const uint32_t sb = smem_u32(smem);
    const uint32_t stage0 = sb + 1024;

    const int tid  = threadIdx.x;
    const int wid  = tid >> 5, lane = tid & 31;
    const int wm   = wid & 3;
    const int wn   = wid >> 2;
    const int mtile = blockIdx.y, ntile = blockIdx.x;

    if (tid == 0) {
#pragma unroll
        for (int s = 0; s < NSTG; ++s) mbar_init(sb + s * 8, 1);
    }
    __syncthreads();

    const unsigned char* aSrc = g_A + ((size_t)mtile * NPAIR << 14);
    const unsigned char* bSrc = g_B + ((size_t)ntile * NPAIR << 14);

    if (tid == 0) {
#pragma unroll
        for (int p = 0; p < NSTG; ++p) {
            uint32_t fb = sb + p * 8;
            uint32_t dst = stage0 + p * STG_B;
            mbar_expect_tx(fb, STG_B);
            bulk_g2s(dst,          aSrc + ((size_t)p << 14), TILE_B, fb);
            bulk_g2s(dst + TILE_B, bSrc + ((size_t)p << 14), TILE_B, fb);
        }
    }

    float acc[2][8][4];
#pragma unroll
    for (int mi = 0; mi < 2; ++mi)
#pragma unroll
        for (int ni = 0; ni < 8; ++ni)
#pragma unroll
            for (int r = 0; r < 4; ++r) acc[mi][ni][r] = 0.0f;

    const int g = lane >> 3, r8 = lane & 7;
    const uint32_t aRow = (uint32_t)(wm * 32 + ((g & 1) << 3) + r8);
    const uint32_t bRow = (uint32_t)(wn * 64 + ((g >> 1) << 3) + r8);
    const uint32_t aKb  = (uint32_t)((g >> 1) << 4);
    const uint32_t bKb  = (uint32_t)((g & 1) << 4);

    for (int k = 0; k < NPAIR; k += 2) {
        // ---- consume chunks k and k+1 (wait kept adjacent to each chunk:
        //      chunk k+1's TMA completes under chunk k's MMAs) ----
#pragma unroll
        for (int c = 0; c < 2; ++c) {
            const int kc = k + c;
            const int sp = kc % NSTG;
            const uint32_t fb = sb + sp * 8;
            mbar_wait(fb, (uint32_t)((kc / NSTG) & 1));

            const uint32_t stA = stage0 + sp * STG_B;
            const uint32_t stB = stA + TILE_B;

#pragma unroll
            for (int ks = 0; ks < 4; ++ks) {
                uint32_t a[2][4];
#pragma unroll
                for (int mi = 0; mi < 2; ++mi) {
                    uint32_t off = (aRow + mi * 16) * 128u + (uint32_t)(ks * 32) + aKb;
                    ldsm_x4(a[mi][0], a[mi][1], a[mi][2], a[mi][3], stA + swz128(off));
                }
                uint32_t b[4][4];
#pragma unroll
                for (int nj = 0; nj < 4; ++nj) {
                    uint32_t off = (bRow + nj * 16) * 128u + (uint32_t)(ks * 32) + bKb;
                    ldsm_x4(b[nj][0], b[nj][1], b[nj][2], b[nj][3], stB + swz128(off));
                }
#pragma unroll
                for (int mi = 0; mi < 2; ++mi)
#pragma unroll
                    for (int ni = 0; ni < 8; ++ni)
                        mma16816(acc[mi][ni], a[mi],
                                 b[ni >> 1][(ni & 1) * 2], b[ni >> 1][(ni & 1) * 2 + 1]);
            }
        }

        __syncthreads();   // all warps done reading stages k%3 and (k+1)%3
        if (tid == 0) {
#pragma unroll
            for (int c = 0; c < 2; ++c) {
                const int kn = k + c + NSTG;
                if (kn < NPAIR) {
                    const int sp = kn % NSTG;      // == (k+c)%3
                    const uint32_t fb = sb + sp * 8;
                    uint32_t dst = stage0 + sp * STG_B;
                    mbar_expect_tx(fb, STG_B);
                    bulk_g2s(dst,          aSrc + ((size_t)kn << 14), TILE_B, fb);
                    bulk_g2s(dst + TILE_B, bSrc + ((size_t)kn << 14), TILE_B, fb);
                }
            }
        }
    }

    // ---------------- epilogue: bias + clamp, float2 stores ------------------
    const int mBase = mtile * MT + wm * 32 + (lane >> 2);
    const int nBase = ntile * NT + wn * 64 + (lane & 3) * 2;

#pragma unroll
    for (int mi = 0; mi < 2; ++mi) {
#pragma unroll
        for (int ni = 0; ni < 8; ++ni) {
            const int n = nBase + ni * 8;
            const float b0 = g_bias[n], b1 = g_bias[n + 1];
            const int m0 = mBase + mi * 16;
            float2 v0, v1;
            v0.x = clampf(acc[mi][ni][0] + b0);
            v0.y = clampf(acc[mi][ni][1] + b1);
            v1.x = clampf(acc[mi][ni][2] + b0);
            v1.y = clampf(acc[mi][ni][3] + b1);
            *reinterpret_cast<float2*>(C + (size_t)m0 * O_DIM + n)       = v0;
            *reinterpret_cast<float2*>(C + (size_t)(m0 + 8) * O_DIM + n) = v1;
        }
    }
}

// ---------------------------------------------------------------------------
extern "C" void kernel_launch(void* const* d_in, const int* in_sizes, int n_in,
                              void* d_out, int out_size) {
    const float* x      = (const float*)d_in[0];
    const float* coeffs = (const float*)d_in[1];
    float* out          = (float*)d_out;

    cudaFuncSetAttribute(gemm_kernel, cudaFuncAttributeMaxDynamicSharedMemorySize, SMEM_TOTAL);

    prep_kernel<<<FEAT_BLOCKS + O_DIM, 256>>>(x, coeffs);
    gemm_kernel<<<dim3(O_DIM / NT, N_ROWS / MT), 256, SMEM_TOTAL>>>(out);
}